// round 1
// baseline (speedup 1.0000x reference)
#include <cuda_runtime.h>
#include <math.h>

#define Bc 4
#define Nc 5
#define Cc 64
#define Hc 100
#define Wc 252

static constexpr int HW  = Hc * Wc;      // 25200
static constexpr int CHW = Cc * HW;      // 1612800
static constexpr int OUT_MAIN = Bc * CHW;

__global__ __launch_bounds__(256) void where2comm_fuse_kernel(
    const float* __restrict__ x,          // [B*N, C, H, W]
    const float* __restrict__ tmat,       // [B, N, N, 2, 3]
    float* __restrict__ out,              // [B, C, H, W] (+ scalar tail)
    int out_size)
{
    const int h = blockIdx.x;
    const int b = blockIdx.y;
    const int w = threadIdx.x;

    // Zero any tail (communication_rates scalar) once.
    if (b == 0 && h == 0) {
        for (int i = OUT_MAIN + threadIdx.x; i < out_size; i += blockDim.x)
            out[i] = 0.0f;
    }
    if (w >= Wc) return;

    const float gx = (2.0f * (float)w + 1.0f) / (float)Wc - 1.0f;
    const float gy = (2.0f * (float)h + 1.0f) / (float)Hc - 1.0f;

    int   offs[Nc][4];
    float wts [Nc][4];

#pragma unroll
    for (int n = 0; n < Nc; n++) {
        // theta = pairwise_t_matrix[b, 0, n, :, :]  -> 6 floats
        const float* th = tmat + ((size_t)b * Nc * Nc + n) * 6;
        const float t0 = __ldg(th + 0);
        const float t1 = __ldg(th + 1);
        const float t2 = __ldg(th + 2);
        const float t3 = __ldg(th + 3);
        const float t4 = __ldg(th + 4);
        const float t5 = __ldg(th + 5);

        const float cx = t0 * gx + t1 * gy + t2;
        const float cy = t3 * gx + t4 * gy + t5;
        const float ix = ((cx + 1.0f) * (float)Wc - 1.0f) * 0.5f;
        const float iy = ((cy + 1.0f) * (float)Hc - 1.0f) * 0.5f;

        const float x0f = floorf(ix);
        const float y0f = floorf(iy);
        const float wx1 = ix - x0f;
        const float wy1 = iy - y0f;
        const float wx0 = 1.0f - wx1;
        const float wy0 = 1.0f - wy1;

        const int x0 = (int)x0f;
        const int y0 = (int)y0f;
        const int x1 = x0 + 1;
        const int y1 = y0 + 1;

        const bool vx0 = (x0 >= 0) & (x0 <= Wc - 1);
        const bool vx1 = (x1 >= 0) & (x1 <= Wc - 1);
        const bool vy0 = (y0 >= 0) & (y0 <= Hc - 1);
        const bool vy1 = (y1 >= 0) & (y1 <= Hc - 1);

        const int x0c = min(max(x0, 0), Wc - 1);
        const int x1c = min(max(x1, 0), Wc - 1);
        const int y0c = min(max(y0, 0), Hc - 1);
        const int y1c = min(max(y1, 0), Hc - 1);

        const int base = (b * Nc + n) * CHW;
        offs[n][0] = base + y0c * Wc + x0c;
        offs[n][1] = base + y0c * Wc + x1c;
        offs[n][2] = base + y1c * Wc + x0c;
        offs[n][3] = base + y1c * Wc + x1c;

        wts[n][0] = (vx0 && vy0) ? wx0 * wy0 : 0.0f;
        wts[n][1] = (vx1 && vy0) ? wx1 * wy0 : 0.0f;
        wts[n][2] = (vx0 && vy1) ? wx0 * wy1 : 0.0f;
        wts[n][3] = (vx1 && vy1) ? wx1 * wy1 : 0.0f;
    }

    float* op = out + (size_t)b * CHW + h * Wc + w;

#pragma unroll 2
    for (int c = 0; c < Cc; c++) {
        const int coff = c * HW;
        float m = -INFINITY;
#pragma unroll
        for (int n = 0; n < Nc; n++) {
            float v = wts[n][0] * __ldg(x + offs[n][0] + coff);
            v = fmaf(wts[n][1], __ldg(x + offs[n][1] + coff), v);
            v = fmaf(wts[n][2], __ldg(x + offs[n][2] + coff), v);
            v = fmaf(wts[n][3], __ldg(x + offs[n][3] + coff), v);
            m = fmaxf(m, v);
        }
        op[(size_t)coff] = m;
    }
}

extern "C" void kernel_launch(void* const* d_in, const int* in_sizes, int n_in,
                              void* d_out, int out_size)
{
    // Inputs (metadata order): x, rm, record_len, pairwise_t_matrix
    const float* x    = (const float*)d_in[0];
    const float* tmat = (const float*)d_in[3];
    float* out = (float*)d_out;

    dim3 grid(Hc, Bc);
    where2comm_fuse_kernel<<<grid, 256>>>(x, tmat, out, out_size);
}

// round 2
// speedup vs baseline: 1.0271x; 1.0271x over previous
#include <cuda_runtime.h>
#include <math.h>

#define Bc 4
#define Nc 5
#define Cc 64
#define Hc 100
#define Wc 252

static constexpr int HW  = Hc * Wc;      // 25200
static constexpr int CHW = Cc * HW;      // 1612800
static constexpr int OUT_MAIN = Bc * CHW;
static constexpr int C_CHUNKS = 4;
static constexpr int C_PER    = Cc / C_CHUNKS;   // 16

__global__ __launch_bounds__(256) void where2comm_fuse_kernel(
    const float* __restrict__ x,          // [B*N, C, H, W]
    const float* __restrict__ tmat,       // [B, N, N, 2, 3]
    float* __restrict__ out,              // [B, C, H, W] (+ scalar tail)
    int out_size)
{
    const int h  = blockIdx.x;
    const int b  = blockIdx.y;
    const int c0 = blockIdx.z * C_PER;
    const int w  = threadIdx.x;

    // Zero any tail (communication_rates scalar) once.
    if (b == 0 && h == 0 && blockIdx.z == 0) {
        for (int i = OUT_MAIN + threadIdx.x; i < out_size; i += blockDim.x)
            out[i] = 0.0f;
    }
    if (w >= Wc) return;

    const float gx = (2.0f * (float)w + 1.0f) / (float)Wc - 1.0f;
    const float gy = (2.0f * (float)h + 1.0f) / (float)Hc - 1.0f;

    int   offs[Nc][4];
    float wts [Nc][4];

#pragma unroll
    for (int n = 0; n < Nc; n++) {
        // theta = pairwise_t_matrix[b, 0, n, :, :]  -> 6 floats
        const float* th = tmat + ((size_t)b * Nc * Nc + n) * 6;
        const float t0 = __ldg(th + 0);
        const float t1 = __ldg(th + 1);
        const float t2 = __ldg(th + 2);
        const float t3 = __ldg(th + 3);
        const float t4 = __ldg(th + 4);
        const float t5 = __ldg(th + 5);

        const float cx = t0 * gx + t1 * gy + t2;
        const float cy = t3 * gx + t4 * gy + t5;
        const float ix = ((cx + 1.0f) * (float)Wc - 1.0f) * 0.5f;
        const float iy = ((cy + 1.0f) * (float)Hc - 1.0f) * 0.5f;

        const float x0f = floorf(ix);
        const float y0f = floorf(iy);
        const float wx1 = ix - x0f;
        const float wy1 = iy - y0f;
        const float wx0 = 1.0f - wx1;
        const float wy0 = 1.0f - wy1;

        const int x0 = (int)x0f;
        const int y0 = (int)y0f;
        const int x1 = x0 + 1;
        const int y1 = y0 + 1;

        const bool vx0 = (x0 >= 0) & (x0 <= Wc - 1);
        const bool vx1 = (x1 >= 0) & (x1 <= Wc - 1);
        const bool vy0 = (y0 >= 0) & (y0 <= Hc - 1);
        const bool vy1 = (y1 >= 0) & (y1 <= Hc - 1);

        const int x0c = min(max(x0, 0), Wc - 1);
        const int x1c = min(max(x1, 0), Wc - 1);
        const int y0c = min(max(y0, 0), Hc - 1);
        const int y1c = min(max(y1, 0), Hc - 1);

        const int base = (b * Nc + n) * CHW + c0 * HW;
        offs[n][0] = base + y0c * Wc + x0c;
        offs[n][1] = base + y0c * Wc + x1c;
        offs[n][2] = base + y1c * Wc + x0c;
        offs[n][3] = base + y1c * Wc + x1c;

        wts[n][0] = (vx0 && vy0) ? wx0 * wy0 : 0.0f;
        wts[n][1] = (vx1 && vy0) ? wx1 * wy0 : 0.0f;
        wts[n][2] = (vx0 && vy1) ? wx0 * wy1 : 0.0f;
        wts[n][3] = (vx1 && vy1) ? wx1 * wy1 : 0.0f;
    }

    float* op = out + (size_t)b * CHW + (size_t)c0 * HW + h * Wc + w;

#pragma unroll 4
    for (int c = 0; c < C_PER; c++) {
        const int coff = c * HW;
        float m = -INFINITY;
#pragma unroll
        for (int n = 0; n < Nc; n++) {
            float v = wts[n][0] * __ldg(x + offs[n][0] + coff);
            v = fmaf(wts[n][1], __ldg(x + offs[n][1] + coff), v);
            v = fmaf(wts[n][2], __ldg(x + offs[n][2] + coff), v);
            v = fmaf(wts[n][3], __ldg(x + offs[n][3] + coff), v);
            m = fmaxf(m, v);
        }
        op[(size_t)coff] = m;
    }
}

extern "C" void kernel_launch(void* const* d_in, const int* in_sizes, int n_in,
                              void* d_out, int out_size)
{
    // Inputs (metadata order): x, rm, record_len, pairwise_t_matrix
    const float* x    = (const float*)d_in[0];
    const float* tmat = (const float*)d_in[3];
    float* out = (float*)d_out;

    dim3 grid(Hc, Bc, C_CHUNKS);
    where2comm_fuse_kernel<<<grid, 256>>>(x, tmat, out, out_size);
}

// round 3
// speedup vs baseline: 1.6405x; 1.5972x over previous
#include <cuda_runtime.h>
#include <math.h>

#define Bc 4
#define Nc 5
#define Cc 64
#define Hc 100
#define Wc 252

static constexpr int HW  = Hc * Wc;      // 25200
static constexpr int CHW = Cc * HW;      // 1612800
static constexpr int OUT_MAIN = Bc * CHW;
static constexpr int C_CHUNKS = 4;
static constexpr int C_PER    = Cc / C_CHUNKS;   // 16

__global__ __launch_bounds__(256, 4) void where2comm_fuse_kernel(
    const float* __restrict__ x,          // [B*N, C, H, W]
    const float* __restrict__ tmat,       // [B, N, N, 2, 3]
    float* __restrict__ out,              // [B, C, H, W] (+ scalar tail)
    int out_size)
{
    const int h  = blockIdx.x;
    const int b  = blockIdx.y;
    const int c0 = blockIdx.z * C_PER;
    const int w  = threadIdx.x;

    // Zero any tail (communication_rates scalar) once.
    if (b == 0 && h == 0 && blockIdx.z == 0) {
        for (int i = OUT_MAIN + threadIdx.x; i < out_size; i += blockDim.x)
            out[i] = 0.0f;
    }
    if (w >= Wc) return;

    const float gx = (2.0f * (float)w + 1.0f) / (float)Wc - 1.0f;
    const float gy = (2.0f * (float)h + 1.0f) / (float)Hc - 1.0f;

    float m[C_PER];
#pragma unroll
    for (int c = 0; c < C_PER; c++) m[c] = -INFINITY;

#pragma unroll
    for (int n = 0; n < Nc; n++) {
        // theta = pairwise_t_matrix[b, 0, n, :, :]  -> 6 floats
        const float* th = tmat + ((size_t)b * Nc * Nc + n) * 6;
        const float t0 = __ldg(th + 0);
        const float t1 = __ldg(th + 1);
        const float t2 = __ldg(th + 2);
        const float t3 = __ldg(th + 3);
        const float t4 = __ldg(th + 4);
        const float t5 = __ldg(th + 5);

        const float cx = t0 * gx + t1 * gy + t2;
        const float cy = t3 * gx + t4 * gy + t5;
        const float ix = ((cx + 1.0f) * (float)Wc - 1.0f) * 0.5f;
        const float iy = ((cy + 1.0f) * (float)Hc - 1.0f) * 0.5f;

        const float x0f = floorf(ix);
        const float y0f = floorf(iy);
        const float wx1 = ix - x0f;
        const float wy1 = iy - y0f;
        const float wx0 = 1.0f - wx1;
        const float wy0 = 1.0f - wy1;

        const int x0 = (int)x0f;
        const int y0 = (int)y0f;
        const int x1 = x0 + 1;
        const int y1 = y0 + 1;

        const bool vx0 = (x0 >= 0) & (x0 <= Wc - 1);
        const bool vx1 = (x1 >= 0) & (x1 <= Wc - 1);
        const bool vy0 = (y0 >= 0) & (y0 <= Hc - 1);
        const bool vy1 = (y1 >= 0) & (y1 <= Hc - 1);

        const int x0c = min(max(x0, 0), Wc - 1);
        const int x1c = min(max(x1, 0), Wc - 1);
        const int y0c = min(max(y0, 0), Hc - 1);
        const int y1c = min(max(y1, 0), Hc - 1);

        const int base = (b * Nc + n) * CHW + c0 * HW;
        const float* p0 = x + base + y0c * Wc + x0c;
        const float* p1 = x + base + y0c * Wc + x1c;
        const float* p2 = x + base + y1c * Wc + x0c;
        const float* p3 = x + base + y1c * Wc + x1c;

        const float w0 = (vx0 && vy0) ? wx0 * wy0 : 0.0f;
        const float w1 = (vx1 && vy0) ? wx1 * wy0 : 0.0f;
        const float w2 = (vx0 && vy1) ? wx0 * wy1 : 0.0f;
        const float w3 = (vx1 && vy1) ? wx1 * wy1 : 0.0f;

#pragma unroll
        for (int c = 0; c < C_PER; c++) {
            const int coff = c * HW;
            float v = w0 * __ldg(p0 + coff);
            v = fmaf(w1, __ldg(p1 + coff), v);
            v = fmaf(w2, __ldg(p2 + coff), v);
            v = fmaf(w3, __ldg(p3 + coff), v);
            m[c] = fmaxf(m[c], v);
        }
    }

    float* op = out + (size_t)b * CHW + (size_t)c0 * HW + h * Wc + w;
#pragma unroll
    for (int c = 0; c < C_PER; c++)
        op[(size_t)c * HW] = m[c];
}

extern "C" void kernel_launch(void* const* d_in, const int* in_sizes, int n_in,
                              void* d_out, int out_size)
{
    // Inputs (metadata order): x, rm, record_len, pairwise_t_matrix
    const float* x    = (const float*)d_in[0];
    const float* tmat = (const float*)d_in[3];
    float* out = (float*)d_out;

    dim3 grid(Hc, Bc, C_CHUNKS);
    where2comm_fuse_kernel<<<grid, 256>>>(x, tmat, out, out_size);
}